// round 9
// baseline (speedup 1.0000x reference)
#include <cuda_runtime.h>
#include <math.h>

#define Bq 2
#define Tt 1024
#define DM 512
#define Hh 8
#define DEP 64
#define NTOK (Bq*Tt)      // 2048
#define BH   (Bq*Hh)      // 16
#define NBHT (BH*Tt)      // 16384

// ---------------- scratch (device globals; no allocation) ----------------
__device__ float g_Q[NTOK*DM];
__device__ float g_K[NTOK*DM];
__device__ float g_V[NTOK*DM];
__device__ float g_Cb[NTOK*DM];
__device__ float g_S[(size_t)BH*Tt*Tt];   // 64 MB candidate scores (tf32 quality)
__device__ float g_wphi[128];
__device__ float g_wtau[128];
__device__ float g_cphi[1];
__device__ float g_ctau[1];
__device__ float g_pq_phi[NBHT], g_pk_phi[NBHT];
__device__ float g_pq_ta [NBHT], g_pk_ta [NBHT];
__device__ float g_pq_tb [NBHT], g_pk_tb [NBHT];
__device__ float g_pq_tau[NBHT], g_pk_tau[NBHT];

// ---------------- packed fp32x2 FMA helpers ----------------
__device__ __forceinline__ void ffma2(unsigned long long &acc, unsigned long long a,
                                      unsigned long long b) {
    asm("fma.rn.f32x2 %0, %1, %2, %0;" : "+l"(acc) : "l"(a), "l"(b));
}
__device__ __forceinline__ unsigned long long pack2(float x, float y) {
    unsigned long long r;
    asm("mov.b64 %0, {%1, %2};" : "=l"(r) : "f"(x), "f"(y));
    return r;
}
__device__ __forceinline__ void unpack2(unsigned long long v, float &x, float &y) {
    asm("mov.b64 {%0, %1}, %2;" : "=f"(x), "=f"(y) : "l"(v));
}

#define MMA8(cc, aa, bb) \
    asm volatile("mma.sync.aligned.m16n8k8.row.col.f32.tf32.tf32.f32 " \
                 "{%0,%1,%2,%3},{%4,%5,%6,%7},{%8,%9},{%0,%1,%2,%3};" \
                 : "+f"(cc[0]), "+f"(cc[1]), "+f"(cc[2]), "+f"(cc[3]) \
                 : "r"(aa.x), "r"(aa.y), "r"(aa.z), "r"(aa.w), "r"(bb.x), "r"(bb.y))

// ---------------- 1. collapse the linear-linear per-pair MLPs (warp per output) ----------------
__global__ void combine_kernel(const float* __restrict__ Wpi, const float* __restrict__ bpi,
                               const float* __restrict__ Wpo, const float* __restrict__ bpo,
                               const float* __restrict__ Wti, const float* __restrict__ bti,
                               const float* __restrict__ Wto, const float* __restrict__ bto) {
    const unsigned FULL = 0xffffffffu;
    int w    = (blockIdx.x * blockDim.x + threadIdx.x) >> 5;   // 0..159
    int lane = threadIdx.x & 31;
    if (w < 128) {
        float s = 0.f;
        for (int m = lane; m < 512; m += 32) s += Wpi[w*512 + m] * Wpo[m];
        float s2 = 0.f;
        for (int m = lane; m < 256; m += 32) s2 += Wti[w*256 + m] * Wto[m];
        #pragma unroll
        for (int off = 16; off; off >>= 1) {
            s  += __shfl_xor_sync(FULL, s,  off);
            s2 += __shfl_xor_sync(FULL, s2, off);
        }
        if (lane == 0) { g_wphi[w] = s; g_wtau[w] = s2; }
    } else if (w == 128) {
        float c = 0.f;
        for (int m = lane; m < 512; m += 32) c += bpi[m] * Wpo[m];
        #pragma unroll
        for (int off = 16; off; off >>= 1) c += __shfl_xor_sync(FULL, c, off);
        if (lane == 0) g_cphi[0] = c + bpo[0];
    } else if (w == 129) {
        float c2 = 0.f;
        for (int m = lane; m < 256; m += 32) c2 += bti[m] * Wto[m];
        #pragma unroll
        for (int off = 16; off; off >>= 1) c2 += __shfl_xor_sync(FULL, c2, off);
        if (lane == 0) g_ctau[0] = c2 + bto[0];
    }
}

// ---------------- 2. fp32 GEMM (FFMA2): C[2048,512] = A @ W + bias, z-mux over 3 ----------------
__global__ void __launch_bounds__(256, 3)
gemm_bias3(const float* __restrict__ A,
           const float* __restrict__ W0, const float* __restrict__ b0, float* __restrict__ C0,
           const float* __restrict__ W1, const float* __restrict__ b1, float* __restrict__ C1,
           const float* __restrict__ W2, const float* __restrict__ b2, float* __restrict__ C2) {
    __shared__ float As[16][132];
    __shared__ float Ws[16][68];
    const int tid = threadIdx.x;
    const int tx = tid & 15, ty = tid >> 4;
    const int m0 = blockIdx.y * 128, n0 = blockIdx.x * 64;
    const int z = blockIdx.z;
    const float* W  = (z == 0) ? W0 : (z == 1) ? W1 : W2;
    const float* bi = (z == 0) ? b0 : (z == 1) ? b1 : b2;
    float*       C  = (z == 0) ? C0 : (z == 1) ? C1 : C2;

    const int ar   = tid >> 1;
    const int ah   = (tid & 1) * 8;
    const int wkk  = tid >> 4;
    const int wn   = (tid & 15) * 4;

    unsigned long long accp[4][4] = {};
    for (int k0 = 0; k0 < 512; k0 += 16) {
        const float* ap2 = A + (size_t)(m0 + ar) * 512 + k0 + ah;
        float4 a0 = *(const float4*)(ap2);
        float4 a1 = *(const float4*)(ap2 + 4);
        As[ah + 0][ar] = a0.x; As[ah + 1][ar] = a0.y;
        As[ah + 2][ar] = a0.z; As[ah + 3][ar] = a0.w;
        As[ah + 4][ar] = a1.x; As[ah + 5][ar] = a1.y;
        As[ah + 6][ar] = a1.z; As[ah + 7][ar] = a1.w;
        *(float4*)&Ws[wkk][wn] = *(const float4*)(W + (size_t)(k0 + wkk) * 512 + n0 + wn);
        __syncthreads();
        #pragma unroll
        for (int kk = 0; kk < 16; kk++) {
            float a[8], w[4];
            *(float4*)(a)     = *(float4*)&As[kk][ty*8];
            *(float4*)(a + 4) = *(float4*)&As[kk][ty*8 + 4];
            *(float4*)(w)     = *(float4*)&Ws[kk][tx*4];
            unsigned long long ap[4], wd[4];
            #pragma unroll
            for (int ip = 0; ip < 4; ip++) ap[ip] = pack2(a[2*ip], a[2*ip+1]);
            #pragma unroll
            for (int j = 0; j < 4; j++) wd[j] = pack2(w[j], w[j]);
            #pragma unroll
            for (int ip = 0; ip < 4; ip++)
                #pragma unroll
                for (int j = 0; j < 4; j++)
                    ffma2(accp[ip][j], ap[ip], wd[j]);
        }
        __syncthreads();
    }
    float4 bv = *(const float4*)(bi + n0 + tx*4);
    #pragma unroll
    for (int ip = 0; ip < 4; ip++) {
        float r0[4], r1[4];
        #pragma unroll
        for (int j = 0; j < 4; j++) unpack2(accp[ip][j], r0[j], r1[j]);
        float4 o0, o1;
        o0.x = r0[0] + bv.x; o0.y = r0[1] + bv.y; o0.z = r0[2] + bv.z; o0.w = r0[3] + bv.w;
        o1.x = r1[0] + bv.x; o1.y = r1[1] + bv.y; o1.z = r1[2] + bv.z; o1.w = r1[3] + bv.w;
        *(float4*)(C + (size_t)(m0 + ty*8 + 2*ip)     * 512 + n0 + tx*4) = o0;
        *(float4*)(C + (size_t)(m0 + ty*8 + 2*ip + 1) * 512 + n0 + tx*4) = o1;
    }
}

// ---------------- 3. per-token feature scalars (one warp per (b,h,t)) ----------------
__global__ void token_kernel(const float* __restrict__ Wta, const float* __restrict__ bta,
                             const float* __restrict__ Wtb, const float* __restrict__ btb) {
    int gw   = (blockIdx.x * blockDim.x + threadIdx.x) >> 5;
    int lane = threadIdx.x & 31;
    if (gw >= NBHT) return;
    int bh = gw >> 10, t = gw & 1023;
    int b = bh >> 3, h = bh & 7;
    size_t base = ((size_t)(b*Tt + t))*DM + h*DEP;
    float q0 = g_Q[base+lane], q1 = g_Q[base+lane+32];
    float k0 = g_K[base+lane], k1 = g_K[base+lane+32];

    float sphiq = q0*g_wphi[lane]    + q1*g_wphi[lane+32];
    float sphik = k0*g_wphi[64+lane] + k1*g_wphi[96+lane];
    float staq  = q0*Wta[lane]       + q1*Wta[lane+32];
    float stak  = k0*Wta[64+lane]    + k1*Wta[96+lane];
    float stbq  = q0*Wtb[lane]       + q1*Wtb[lane+32];
    float stbk  = k0*Wtb[64+lane]    + k1*Wtb[96+lane];
    float stauq = q0*g_wtau[lane]    + q1*g_wtau[lane+32];
    float stauk = k0*g_wtau[64+lane] + k1*g_wtau[96+lane];

    #pragma unroll
    for (int off = 16; off; off >>= 1) {
        sphiq += __shfl_xor_sync(0xffffffffu, sphiq, off);
        sphik += __shfl_xor_sync(0xffffffffu, sphik, off);
        staq  += __shfl_xor_sync(0xffffffffu, staq,  off);
        stak  += __shfl_xor_sync(0xffffffffu, stak,  off);
        stbq  += __shfl_xor_sync(0xffffffffu, stbq,  off);
        stbk  += __shfl_xor_sync(0xffffffffu, stbk,  off);
        stauq += __shfl_xor_sync(0xffffffffu, stauq, off);
        stauk += __shfl_xor_sync(0xffffffffu, stauk, off);
    }
    if (lane == 0) {
        g_pq_phi[gw] = sphiq + g_cphi[0];
        g_pk_phi[gw] = sphik;
        g_pq_ta [gw] = staq + bta[0];
        g_pk_ta [gw] = stak;
        g_pq_tb [gw] = stbq + btb[0];
        g_pk_tb [gw] = stbk;
        g_pq_tau[gw] = stauq + g_ctau[0];
        g_pk_tau[gw] = stauk;
    }
}

// ---------------- 4. candidate scores via tf32 MMA (selection-only quality) ----------------
// S[bh][q][j] = q.k at tf32 precision. Tile 128q x 64j, K=64 fully staged.
__global__ void __launch_bounds__(256, 3) cand_scores() {
    __shared__ float As[8192];   // 128x64, fragment-ordered: tile(mt*8+kt)*128 + lane*4 + reg
    __shared__ float Bs[4096];   // 64x64:  tile(nt*8+kt)*64 + lane*2 + reg
    const int tid = threadIdx.x, lane = tid & 31, warp = tid >> 5;
    const int wm = warp & 3, wn = warp >> 2;
    const int bh = blockIdx.z, b = bh >> 3, h = bh & 7;
    const int j0 = blockIdx.x * 64, q0 = blockIdx.y * 128;
    const float* Qb = g_Q + (size_t)b*Tt*DM + h*DEP;
    const float* Kb = g_K + (size_t)b*Tt*DM + h*DEP;

    #pragma unroll
    for (int i = 0; i < 32; i++) {
        int s = tid + i*256;                 // 0..8191
        int tile = s >> 7, mt = tile >> 3, kt = tile & 7;
        int ln = (s >> 2) & 31, reg = s & 3;
        int r = (ln >> 2) + ((reg & 1) << 3);
        int c = (ln & 3) + ((reg & 2) << 1);
        As[s] = __ldg(Qb + (size_t)(q0 + mt*16 + r)*DM + kt*8 + c);
    }
    #pragma unroll
    for (int i = 0; i < 16; i++) {
        int s = tid + i*256;                 // 0..4095
        int tile = s >> 6, nt = tile >> 3, kt = tile & 7;
        int ln = (s >> 1) & 31, reg = s & 1;
        int n = ln >> 2;
        int k = (ln & 3) + (reg << 2);
        Bs[s] = __ldg(Kb + (size_t)(j0 + nt*8 + n)*DM + kt*8 + k);
    }
    __syncthreads();

    float acc[2][4][4] = {};
    #pragma unroll
    for (int kt = 0; kt < 8; kt++) {
        uint4 a[2];
        #pragma unroll
        for (int t = 0; t < 2; t++)
            a[t] = *(const uint4*)&As[((wm*2 + t)*8 + kt)*128 + lane*4];
        uint2 bb[4];
        #pragma unroll
        for (int t = 0; t < 4; t++)
            bb[t] = *(const uint2*)&Bs[((wn*4 + t)*8 + kt)*64 + lane*2];
        #pragma unroll
        for (int i = 0; i < 2; i++)
            #pragma unroll
            for (int j = 0; j < 4; j++)
                MMA8(acc[i][j], a[i], bb[j]);
    }

    const int gid = lane >> 2, tig = lane & 3;
    float* Srow = g_S + (size_t)bh*Tt*Tt;
    #pragma unroll
    for (int i = 0; i < 2; i++) {
        int m = q0 + wm*32 + i*16 + gid;
        #pragma unroll
        for (int j = 0; j < 4; j++) {
            int n = j0 + wn*32 + j*8 + tig*2;
            *(float2*)&Srow[(size_t)m*Tt + n]     = make_float2(acc[i][j][0], acc[i][j][1]);
            *(float2*)&Srow[(size_t)(m+8)*Tt + n] = make_float2(acc[i][j][2], acc[i][j][3]);
        }
    }
}

// ---------------- 5. top-32 candidates -> exact fp32 rescore -> exact top-16 ----------------
__device__ __forceinline__ unsigned fmap(float f) {
    unsigned b = __float_as_uint(f);
    return b ^ (((unsigned)((int)b >> 31)) | 0x80000000u);
}

__global__ void attn_kernel() {
    __shared__ float sc[8][1056];    // per-warp 32 classes x 33 stride
    const unsigned FULL = 0xffffffffu;
    int warp = threadIdx.x >> 5, lane = threadIdx.x & 31;
    int wq = blockIdx.x * 8 + warp;
    int bh = wq >> 10, q = wq & 1023;
    int b = bh >> 3, h = bh & 7;

    const float* srow = g_S + ((size_t)bh*Tt + q)*Tt;
    float* s = sc[warp];
    #pragma unroll
    for (int u = 0; u < 8; u++) {
        int i = u*128 + lane*4;
        float4 v = *(const float4*)(srow + i);
        int hi = i >> 5;
        s[((i+0)&31)*33 + hi] = v.x;
        s[((i+1)&31)*33 + hi] = v.y;
        s[((i+2)&31)*33 + hi] = v.z;
        s[((i+3)&31)*33 + hi] = v.w;
    }
    __syncwarp();

    float segv = -INFINITY; int segu = 0;
    #pragma unroll
    for (int u = 0; u < 32; u++) {
        float v = s[lane*33 + u];
        if (v > segv) { segv = v; segu = u; }
    }

    // --- top-32 candidate tournament over tf32 scores (lane r holds candidate r) ---
    int cand = 0;
    #pragma unroll 1
    for (int r = 0; r < 32; r++) {
        unsigned uv = fmap(segv);
        unsigned mx = __reduce_max_sync(FULL, uv);
        int jcand = (uv == mx) ? (segu*32 + lane) : 0x7fffffff;
        int bj = (int)__reduce_min_sync(FULL, (unsigned)jcand);
        if (lane == r) cand = bj;
        int wr = bj & 31, wu = bj >> 5;
        if (lane == wu) s[wr*33 + wu] = -INFINITY;
        __syncwarp();
        float v = s[wr*33 + lane];
        unsigned uv2 = fmap(v);
        unsigned mx2 = __reduce_max_sync(FULL, uv2);
        int ucand = (uv2 == mx2) ? lane : 32;
        int nu = (int)__reduce_min_sync(FULL, (unsigned)ucand);
        float nv = __shfl_sync(FULL, v, nu);
        if (lane == wr) { segv = nv; segu = nu; }
        __syncwarp();
    }

    // --- exact fp32 rescore of my candidate (sequential-d FFMA chain) ---
    const float* qp = g_Q + ((size_t)(b*Tt + q))*DM + h*DEP;
    const float* kp = g_K + ((size_t)(b*Tt + cand))*DM + h*DEP;
    float sx = 0.f;
    #pragma unroll
    for (int u = 0; u < 16; u++) {
        float4 qv = *(const float4*)(qp + u*4);
        float4 kv = *(const float4*)(kp + u*4);
        sx = fmaf(qv.x, kv.x, sx);
        sx = fmaf(qv.y, kv.y, sx);
        sx = fmaf(qv.z, kv.z, sx);
        sx = fmaf(qv.w, kv.w, sx);
    }

    // --- exact top-16 of the 32 rescored candidates (value desc, index-asc ties) ---
    float myv = sx;
    int jsel = 0;
    #pragma unroll 1
    for (int l = 0; l < 16; l++) {
        unsigned uv = fmap(myv);
        unsigned mx = __reduce_max_sync(FULL, uv);
        int jc = (uv == mx) ? cand : 0x7fffffff;
        int bj = (int)__reduce_min_sync(FULL, (unsigned)jc);
        if (lane == l) jsel = bj;
        if (cand == bj) myv = -INFINITY;   // candidates are distinct -> exactly one lane
    }

    // --- logits for the 16 selected keys (lanes 0..15) ---
    float logit = -INFINITY;
    int pqi = bh*1024 + q;
    if (lane < 16) {
        int pki = bh*1024 + jsel;
        float aphi = g_pq_phi[pqi] + g_pk_phi[pki];
        float phi  = 1.f / (1.f + expf(-aphi));
        float ta   = g_pq_ta[pqi]  + g_pk_ta[pki];
        float tb   = g_pq_tb[pqi]  + g_pk_tb[pki];
        float ti   = 1.f / (1.f + expf(-(ta + tb)));      // t_scalar = 1
        float xt   = g_pq_tau[pqi] + g_pk_tau[pki];
        float sp   = (xt > 20.f) ? xt : log1pf(expf(xt)); // softplus
        float tau  = sp + 1e-6f;
        logit = phi / tau * (1.f - expf(-tau * ti));
    }
    float m = logit;
    #pragma unroll
    for (int off = 16; off; off >>= 1) m = fmaxf(m, __shfl_xor_sync(FULL, m, off));
    float e = (lane < 16) ? expf(logit - m) : 0.f;
    float ssum = e;
    #pragma unroll
    for (int off = 16; off; off >>= 1) ssum += __shfl_xor_sync(FULL, ssum, off);
    float aw = e / ssum;

    float acc0 = 0.f, acc1 = 0.f;
    #pragma unroll
    for (int l = 0; l < 16; l++) {
        float a = __shfl_sync(FULL, aw,   l);
        int   j = __shfl_sync(FULL, jsel, l);
        const float* vp = g_V + ((size_t)(b*Tt + j))*DM + h*DEP;
        acc0 += a * vp[lane];
        acc1 += a * vp[lane+32];
    }
    float* op = g_Cb + ((size_t)(b*Tt + q))*DM + h*DEP;
    op[lane]    = acc0;   // DT = 1
    op[lane+32] = acc1;
}

// ---------------- launch ----------------
extern "C" void kernel_launch(void* const* d_in, const int* in_sizes, int n_in,
                              void* d_out, int out_size) {
    const float* x   = (const float*)d_in[0];
    const float* Wq  = (const float*)d_in[1];
    const float* bq  = (const float*)d_in[2];
    const float* Wk  = (const float*)d_in[3];
    const float* bk  = (const float*)d_in[4];
    const float* Wv  = (const float*)d_in[5];
    const float* bv  = (const float*)d_in[6];
    const float* Wo  = (const float*)d_in[7];
    const float* bo  = (const float*)d_in[8];
    const float* Wpi = (const float*)d_in[9];
    const float* bpi = (const float*)d_in[10];
    const float* Wpo = (const float*)d_in[11];
    const float* bpo = (const float*)d_in[12];
    const float* Wta = (const float*)d_in[13];
    const float* bta = (const float*)d_in[14];
    const float* Wtb = (const float*)d_in[15];
    const float* btb = (const float*)d_in[16];
    const float* Wti = (const float*)d_in[17];
    const float* bti = (const float*)d_in[18];
    const float* Wto = (const float*)d_in[19];
    const float* bto = (const float*)d_in[20];

    float *Qp, *Kp, *Vp, *Cbp;
    cudaGetSymbolAddress((void**)&Qp,  g_Q);
    cudaGetSymbolAddress((void**)&Kp,  g_K);
    cudaGetSymbolAddress((void**)&Vp,  g_V);
    cudaGetSymbolAddress((void**)&Cbp, g_Cb);

    combine_kernel<<<5, 1024>>>(Wpi, bpi, Wpo, bpo, Wti, bti, Wto, bto);

    gemm_bias3<<<dim3(8, 16, 3), 256>>>(x, Wq, bq, Qp, Wk, bk, Kp, Wv, bv, Vp);

    token_kernel<<<NBHT/8, 256>>>(Wta, bta, Wtb, btb);

    cand_scores<<<dim3(16, 8, 16), 256>>>();

    attn_kernel<<<NBHT/8, 256>>>();

    gemm_bias3<<<dim3(8, 16, 1), 256>>>(Cbp, Wo, bo, (float*)d_out,
                                        Wo, bo, (float*)d_out, Wo, bo, (float*)d_out);
}

// round 11
// speedup vs baseline: 1.0785x; 1.0785x over previous
#include <cuda_runtime.h>
#include <math.h>

#define Bq 2
#define Tt 1024
#define DM 512
#define Hh 8
#define DEP 64
#define NTOK (Bq*Tt)      // 2048
#define BH   (Bq*Hh)      // 16
#define NBHT (BH*Tt)      // 16384
#define NCAND 24

// ---------------- scratch (device globals; no allocation) ----------------
__device__ float g_Q[NTOK*DM];
__device__ float g_K[NTOK*DM];
__device__ float g_V[NTOK*DM];
__device__ float g_Cb[NTOK*DM];
__device__ float g_S[(size_t)BH*Tt*Tt];   // 64 MB candidate scores (tf32 quality)
__device__ float g_wphi[128];
__device__ float g_wtau[128];
__device__ float g_cphi[1];
__device__ float g_ctau[1];
__device__ float g_pq_phi[NBHT], g_pk_phi[NBHT];
__device__ float g_pq_ta [NBHT], g_pk_ta [NBHT];
__device__ float g_pq_tb [NBHT], g_pk_tb [NBHT];
__device__ float g_pq_tau[NBHT], g_pk_tau[NBHT];

// ---------------- packed fp32x2 FMA helpers ----------------
__device__ __forceinline__ void ffma2(unsigned long long &acc, unsigned long long a,
                                      unsigned long long b) {
    asm("fma.rn.f32x2 %0, %1, %2, %0;" : "+l"(acc) : "l"(a), "l"(b));
}
__device__ __forceinline__ unsigned long long pack2(float x, float y) {
    unsigned long long r;
    asm("mov.b64 %0, {%1, %2};" : "=l"(r) : "f"(x), "f"(y));
    return r;
}
__device__ __forceinline__ void unpack2(unsigned long long v, float &x, float &y) {
    asm("mov.b64 {%0, %1}, %2;" : "=f"(x), "=f"(y) : "l"(v));
}

#define MMA8(cc, aa, bb) \
    asm volatile("mma.sync.aligned.m16n8k8.row.col.f32.tf32.tf32.f32 " \
                 "{%0,%1,%2,%3},{%4,%5,%6,%7},{%8,%9},{%0,%1,%2,%3};" \
                 : "+f"(cc[0]), "+f"(cc[1]), "+f"(cc[2]), "+f"(cc[3]) \
                 : "r"(aa.x), "r"(aa.y), "r"(aa.z), "r"(aa.w), "r"(bb.x), "r"(bb.y))

// ---------------- 1. collapse the linear-linear per-pair MLPs (warp per output) ----------------
__global__ void combine_kernel(const float* __restrict__ Wpi, const float* __restrict__ bpi,
                               const float* __restrict__ Wpo, const float* __restrict__ bpo,
                               const float* __restrict__ Wti, const float* __restrict__ bti,
                               const float* __restrict__ Wto, const float* __restrict__ bto) {
    const unsigned FULL = 0xffffffffu;
    int w    = (blockIdx.x * blockDim.x + threadIdx.x) >> 5;   // 0..159
    int lane = threadIdx.x & 31;
    if (w < 128) {
        float s = 0.f;
        for (int m = lane; m < 512; m += 32) s += Wpi[w*512 + m] * Wpo[m];
        float s2 = 0.f;
        for (int m = lane; m < 256; m += 32) s2 += Wti[w*256 + m] * Wto[m];
        #pragma unroll
        for (int off = 16; off; off >>= 1) {
            s  += __shfl_xor_sync(FULL, s,  off);
            s2 += __shfl_xor_sync(FULL, s2, off);
        }
        if (lane == 0) { g_wphi[w] = s; g_wtau[w] = s2; }
    } else if (w == 128) {
        float c = 0.f;
        for (int m = lane; m < 512; m += 32) c += bpi[m] * Wpo[m];
        #pragma unroll
        for (int off = 16; off; off >>= 1) c += __shfl_xor_sync(FULL, c, off);
        if (lane == 0) g_cphi[0] = c + bpo[0];
    } else if (w == 129) {
        float c2 = 0.f;
        for (int m = lane; m < 256; m += 32) c2 += bti[m] * Wto[m];
        #pragma unroll
        for (int off = 16; off; off >>= 1) c2 += __shfl_xor_sync(FULL, c2, off);
        if (lane == 0) g_ctau[0] = c2 + bto[0];
    }
}

// ---------------- 2. fp32 GEMM (FFMA2): C[2048,512] = A @ W + bias, z-mux over 3 ----------------
__global__ void __launch_bounds__(256, 3)
gemm_bias3(const float* __restrict__ A,
           const float* __restrict__ W0, const float* __restrict__ b0, float* __restrict__ C0,
           const float* __restrict__ W1, const float* __restrict__ b1, float* __restrict__ C1,
           const float* __restrict__ W2, const float* __restrict__ b2, float* __restrict__ C2) {
    __shared__ float As[16][132];
    __shared__ float Ws[16][68];
    const int tid = threadIdx.x;
    const int tx = tid & 15, ty = tid >> 4;
    const int m0 = blockIdx.y * 128, n0 = blockIdx.x * 64;
    const int z = blockIdx.z;
    const float* W  = (z == 0) ? W0 : (z == 1) ? W1 : W2;
    const float* bi = (z == 0) ? b0 : (z == 1) ? b1 : b2;
    float*       C  = (z == 0) ? C0 : (z == 1) ? C1 : C2;

    const int ar   = tid >> 1;
    const int ah   = (tid & 1) * 8;
    const int wkk  = tid >> 4;
    const int wn   = (tid & 15) * 4;

    unsigned long long accp[4][4] = {};
    for (int k0 = 0; k0 < 512; k0 += 16) {
        const float* ap2 = A + (size_t)(m0 + ar) * 512 + k0 + ah;
        float4 a0 = *(const float4*)(ap2);
        float4 a1 = *(const float4*)(ap2 + 4);
        As[ah + 0][ar] = a0.x; As[ah + 1][ar] = a0.y;
        As[ah + 2][ar] = a0.z; As[ah + 3][ar] = a0.w;
        As[ah + 4][ar] = a1.x; As[ah + 5][ar] = a1.y;
        As[ah + 6][ar] = a1.z; As[ah + 7][ar] = a1.w;
        *(float4*)&Ws[wkk][wn] = *(const float4*)(W + (size_t)(k0 + wkk) * 512 + n0 + wn);
        __syncthreads();
        #pragma unroll
        for (int kk = 0; kk < 16; kk++) {
            float a[8], w[4];
            *(float4*)(a)     = *(float4*)&As[kk][ty*8];
            *(float4*)(a + 4) = *(float4*)&As[kk][ty*8 + 4];
            *(float4*)(w)     = *(float4*)&Ws[kk][tx*4];
            unsigned long long ap[4], wd[4];
            #pragma unroll
            for (int ip = 0; ip < 4; ip++) ap[ip] = pack2(a[2*ip], a[2*ip+1]);
            #pragma unroll
            for (int j = 0; j < 4; j++) wd[j] = pack2(w[j], w[j]);
            #pragma unroll
            for (int ip = 0; ip < 4; ip++)
                #pragma unroll
                for (int j = 0; j < 4; j++)
                    ffma2(accp[ip][j], ap[ip], wd[j]);
        }
        __syncthreads();
    }
    float4 bv = *(const float4*)(bi + n0 + tx*4);
    #pragma unroll
    for (int ip = 0; ip < 4; ip++) {
        float r0[4], r1[4];
        #pragma unroll
        for (int j = 0; j < 4; j++) unpack2(accp[ip][j], r0[j], r1[j]);
        float4 o0, o1;
        o0.x = r0[0] + bv.x; o0.y = r0[1] + bv.y; o0.z = r0[2] + bv.z; o0.w = r0[3] + bv.w;
        o1.x = r1[0] + bv.x; o1.y = r1[1] + bv.y; o1.z = r1[2] + bv.z; o1.w = r1[3] + bv.w;
        *(float4*)(C + (size_t)(m0 + ty*8 + 2*ip)     * 512 + n0 + tx*4) = o0;
        *(float4*)(C + (size_t)(m0 + ty*8 + 2*ip + 1) * 512 + n0 + tx*4) = o1;
    }
}

// ---------------- 3. per-token feature scalars (one warp per (b,h,t)) ----------------
__global__ void token_kernel(const float* __restrict__ Wta, const float* __restrict__ bta,
                             const float* __restrict__ Wtb, const float* __restrict__ btb) {
    int gw   = (blockIdx.x * blockDim.x + threadIdx.x) >> 5;
    int lane = threadIdx.x & 31;
    if (gw >= NBHT) return;
    int bh = gw >> 10, t = gw & 1023;
    int b = bh >> 3, h = bh & 7;
    size_t base = ((size_t)(b*Tt + t))*DM + h*DEP;
    float q0 = g_Q[base+lane], q1 = g_Q[base+lane+32];
    float k0 = g_K[base+lane], k1 = g_K[base+lane+32];

    float sphiq = q0*g_wphi[lane]    + q1*g_wphi[lane+32];
    float sphik = k0*g_wphi[64+lane] + k1*g_wphi[96+lane];
    float staq  = q0*Wta[lane]       + q1*Wta[lane+32];
    float stak  = k0*Wta[64+lane]    + k1*Wta[96+lane];
    float stbq  = q0*Wtb[lane]       + q1*Wtb[lane+32];
    float stbk  = k0*Wtb[64+lane]    + k1*Wtb[96+lane];
    float stauq = q0*g_wtau[lane]    + q1*g_wtau[lane+32];
    float stauk = k0*g_wtau[64+lane] + k1*g_wtau[96+lane];

    #pragma unroll
    for (int off = 16; off; off >>= 1) {
        sphiq += __shfl_xor_sync(0xffffffffu, sphiq, off);
        sphik += __shfl_xor_sync(0xffffffffu, sphik, off);
        staq  += __shfl_xor_sync(0xffffffffu, staq,  off);
        stak  += __shfl_xor_sync(0xffffffffu, stak,  off);
        stbq  += __shfl_xor_sync(0xffffffffu, stbq,  off);
        stbk  += __shfl_xor_sync(0xffffffffu, stbk,  off);
        stauq += __shfl_xor_sync(0xffffffffu, stauq, off);
        stauk += __shfl_xor_sync(0xffffffffu, stauk, off);
    }
    if (lane == 0) {
        g_pq_phi[gw] = sphiq + g_cphi[0];
        g_pk_phi[gw] = sphik;
        g_pq_ta [gw] = staq + bta[0];
        g_pk_ta [gw] = stak;
        g_pq_tb [gw] = stbq + btb[0];
        g_pk_tb [gw] = stbk;
        g_pq_tau[gw] = stauq + g_ctau[0];
        g_pk_tau[gw] = stauk;
    }
}

// ---------------- 4. candidate scores via tf32 MMA (selection-only quality) ----------------
// Coalesced LDG.128 staging into the validated fragment layout; tile strides padded.
#define A_STRIDE 132
#define B_STRIDE 66
#define CS_SMEM ((64*A_STRIDE + 64*B_STRIDE) * 4)

__global__ void __launch_bounds__(256) cand_scores() {
    extern __shared__ float smp[];
    float* As = smp;                 // 64 tiles x 132
    float* Bs = smp + 64*A_STRIDE;   // 64 tiles x 66
    const int tid = threadIdx.x, lane = tid & 31, warp = tid >> 5;
    const int wm = warp & 3, wn = warp >> 2;
    const int bh = blockIdx.z, b = bh >> 3, h = bh & 7;
    const int j0 = blockIdx.x * 64, q0 = blockIdx.y * 128;
    const float* Qb = g_Q + (size_t)b*Tt*DM + h*DEP;
    const float* Kb = g_K + (size_t)b*Tt*DM + h*DEP;

    #pragma unroll
    for (int it = 0; it < 8; it++) {
        int idx = tid + it*256;              // 0..2047 float4s
        int r = idx >> 4, c0 = (idx & 15) << 2;
        float4 v = *(const float4*)(Qb + (size_t)(q0 + r)*DM + c0);
        int tile = (r >> 4)*8 + (c0 >> 3);
        int reg  = ((r >> 3) & 1) + (((c0 >> 2) & 1) << 1);
        int base = tile*A_STRIDE + ((r & 7) << 2)*4 + reg;
        As[base]      = v.x;
        As[base + 4]  = v.y;
        As[base + 8]  = v.z;
        As[base + 12] = v.w;
    }
    #pragma unroll
    for (int it = 0; it < 4; it++) {
        int idx = tid + it*256;              // 0..1023 float4s
        int n = idx >> 4, k0 = (idx & 15) << 2;
        float4 v = *(const float4*)(Kb + (size_t)(j0 + n)*DM + k0);
        int tile = (n >> 3)*8 + (k0 >> 3);
        int reg  = (k0 >> 2) & 1;
        int base = tile*B_STRIDE + ((n & 7) << 2)*2 + reg;
        Bs[base]     = v.x;
        Bs[base + 2] = v.y;
        Bs[base + 4] = v.z;
        Bs[base + 6] = v.w;
    }
    __syncthreads();

    float acc[2][4][4] = {};
    #pragma unroll
    for (int kt = 0; kt < 8; kt++) {
        uint4 a[2];
        #pragma unroll
        for (int t = 0; t < 2; t++)
            a[t] = *(const uint4*)&As[((wm*2 + t)*8 + kt)*A_STRIDE + lane*4];
        uint2 bb[4];
        #pragma unroll
        for (int t = 0; t < 4; t++)
            bb[t] = *(const uint2*)&Bs[((wn*4 + t)*8 + kt)*B_STRIDE + lane*2];
        #pragma unroll
        for (int i = 0; i < 2; i++)
            #pragma unroll
            for (int j = 0; j < 4; j++)
                MMA8(acc[i][j], a[i], bb[j]);
    }

    const int gid = lane >> 2, tig = lane & 3;
    float* Srow = g_S + (size_t)bh*Tt*Tt;
    #pragma unroll
    for (int i = 0; i < 2; i++) {
        int m = q0 + wm*32 + i*16 + gid;
        #pragma unroll
        for (int j = 0; j < 4; j++) {
            int n = j0 + wn*32 + j*8 + tig*2;
            *(float2*)&Srow[(size_t)m*Tt + n]     = make_float2(acc[i][j][0], acc[i][j][1]);
            *(float2*)&Srow[(size_t)(m+8)*Tt + n] = make_float2(acc[i][j][2], acc[i][j][3]);
        }
    }
}

// ---------------- 5. tf32 top-24 candidates -> exact fp32 rescore -> rank-select top-16 ----------------
__device__ __forceinline__ unsigned fmap(float f) {
    unsigned b = __float_as_uint(f);
    return b ^ (((unsigned)((int)b >> 31)) | 0x80000000u);
}

__global__ void attn_kernel() {
    __shared__ float sc[8][1056];    // per-warp 32 classes x 33 stride
    __shared__ float swv[8][16];
    __shared__ int   swj[8][16];
    const unsigned FULL = 0xffffffffu;
    int warp = threadIdx.x >> 5, lane = threadIdx.x & 31;
    int wq = blockIdx.x * 8 + warp;
    int bh = wq >> 10, q = wq & 1023;
    int b = bh >> 3, h = bh & 7;

    const float* srow = g_S + ((size_t)bh*Tt + q)*Tt;
    float* s = sc[warp];
    #pragma unroll
    for (int u = 0; u < 8; u++) {
        int i = u*128 + lane*4;
        float4 v = *(const float4*)(srow + i);
        int hi = i >> 5;
        s[((i+0)&31)*33 + hi] = v.x;
        s[((i+1)&31)*33 + hi] = v.y;
        s[((i+2)&31)*33 + hi] = v.z;
        s[((i+3)&31)*33 + hi] = v.w;
    }
    __syncwarp();

    float segv = -INFINITY; int segu = 0;
    #pragma unroll
    for (int u = 0; u < 32; u++) {
        float v = s[lane*33 + u];
        if (v > segv) { segv = v; segu = u; }
    }

    // --- tf32 top-24 candidate tournament; lane r (<24) holds candidate r ---
    int cand = 0x40000000 + lane;    // distinct sentinels for unused lanes
    #pragma unroll 1
    for (int r = 0; r < NCAND; r++) {
        unsigned uv = fmap(segv);
        unsigned mx = __reduce_max_sync(FULL, uv);
        int jc = (uv == mx) ? (segu*32 + lane) : 0x7fffffff;
        int bj = (int)__reduce_min_sync(FULL, (unsigned)jc);
        if (lane == r) cand = bj;
        int wr = bj & 31, wu = bj >> 5;
        if (lane == wu) s[wr*33 + wu] = -INFINITY;
        __syncwarp();
        float v = s[wr*33 + lane];
        unsigned uv2 = fmap(v);
        unsigned mx2 = __reduce_max_sync(FULL, uv2);
        int uc = (uv2 == mx2) ? lane : 32;
        int nu = (int)__reduce_min_sync(FULL, (unsigned)uc);
        float nv = __shfl_sync(FULL, v, nu);
        if (lane == wr) { segv = nv; segu = nu; }
        __syncwarp();
    }

    // --- exact fp32 rescore of my candidate (sequential-d FFMA chain) ---
    float myv = -INFINITY;
    if (lane < NCAND) {
        const float* qp = g_Q + ((size_t)(b*Tt + q))*DM + h*DEP;
        const float* kp = g_K + ((size_t)(b*Tt + cand))*DM + h*DEP;
        float sx = 0.f;
        #pragma unroll
        for (int u = 0; u < 16; u++) {
            float4 qv = *(const float4*)(qp + u*4);
            float4 kv = *(const float4*)(kp + u*4);
            sx = fmaf(qv.x, kv.x, sx);
            sx = fmaf(qv.y, kv.y, sx);
            sx = fmaf(qv.z, kv.z, sx);
            sx = fmaf(qv.w, kv.w, sx);
        }
        myv = sx;
    }

    // --- all-pairs rank: rank = #{lanes strictly ahead in (value desc, key-index asc)} ---
    int rank = 0;
    #pragma unroll
    for (int off = 1; off < 32; off++) {
        float ov = __shfl_xor_sync(FULL, myv,  off);
        int   oc = __shfl_xor_sync(FULL, cand, off);
        if (ov > myv || (ov == myv && oc < cand)) rank++;
    }
    // lanes >= NCAND have myv = -inf -> rank >= NCAND automatically

    // --- logits for the 16 selected candidates (rank < 16) ---
    float logit = -INFINITY;
    if (rank < 16) {
        int pqi = bh*1024 + q;
        int pki = bh*1024 + cand;
        float aphi = g_pq_phi[pqi] + g_pk_phi[pki];
        float phi  = 1.f / (1.f + expf(-aphi));
        float ta   = g_pq_ta[pqi]  + g_pk_ta[pki];
        float tb   = g_pq_tb[pqi]  + g_pk_tb[pki];
        float ti   = 1.f / (1.f + expf(-(ta + tb)));      // t_scalar = 1
        float xt   = g_pq_tau[pqi] + g_pk_tau[pki];
        float sp   = (xt > 20.f) ? xt : log1pf(expf(xt)); // softplus
        float tau  = sp + 1e-6f;
        logit = phi / tau * (1.f - expf(-tau * ti));
    }
    float m = logit;
    #pragma unroll
    for (int off = 16; off; off >>= 1) m = fmaxf(m, __shfl_xor_sync(FULL, m, off));
    float e = (rank < 16) ? expf(logit - m) : 0.f;
    float ssum = e;
    #pragma unroll
    for (int off = 16; off; off >>= 1) ssum += __shfl_xor_sync(FULL, ssum, off);

    // --- compact selected (weight, key) pairs by rank; gather V ---
    if (rank < 16) {
        swv[warp][rank] = e / ssum;
        swj[warp][rank] = cand;
    }
    __syncwarp();

    float acc0 = 0.f, acc1 = 0.f;
    #pragma unroll
    for (int l = 0; l < 16; l++) {
        float a = swv[warp][l];
        int   j = swj[warp][l];
        const float* vp = g_V + ((size_t)(b*Tt + j))*DM + h*DEP;
        acc0 += a * vp[lane];
        acc1 += a * vp[lane+32];
    }
    float* op = g_Cb + ((size_t)(b*Tt + q))*DM + h*DEP;
    op[lane]    = acc0;   // DT = 1
    op[lane+32] = acc1;
}

// ---------------- launch ----------------
extern "C" void kernel_launch(void* const* d_in, const int* in_sizes, int n_in,
                              void* d_out, int out_size) {
    const float* x   = (const float*)d_in[0];
    const float* Wq  = (const float*)d_in[1];
    const float* bq  = (const float*)d_in[2];
    const float* Wk  = (const float*)d_in[3];
    const float* bk  = (const float*)d_in[4];
    const float* Wv  = (const float*)d_in[5];
    const float* bv  = (const float*)d_in[6];
    const float* Wo  = (const float*)d_in[7];
    const float* bo  = (const float*)d_in[8];
    const float* Wpi = (const float*)d_in[9];
    const float* bpi = (const float*)d_in[10];
    const float* Wpo = (const float*)d_in[11];
    const float* bpo = (const float*)d_in[12];
    const float* Wta = (const float*)d_in[13];
    const float* bta = (const float*)d_in[14];
    const float* Wtb = (const float*)d_in[15];
    const float* btb = (const float*)d_in[16];
    const float* Wti = (const float*)d_in[17];
    const float* bti = (const float*)d_in[18];
    const float* Wto = (const float*)d_in[19];
    const float* bto = (const float*)d_in[20];

    float *Qp, *Kp, *Vp, *Cbp;
    cudaGetSymbolAddress((void**)&Qp,  g_Q);
    cudaGetSymbolAddress((void**)&Kp,  g_K);
    cudaGetSymbolAddress((void**)&Vp,  g_V);
    cudaGetSymbolAddress((void**)&Cbp, g_Cb);

    cudaFuncSetAttribute(cand_scores, cudaFuncAttributeMaxDynamicSharedMemorySize, CS_SMEM);

    combine_kernel<<<5, 1024>>>(Wpi, bpi, Wpo, bpo, Wti, bti, Wto, bto);

    gemm_bias3<<<dim3(8, 16, 3), 256>>>(x, Wq, bq, Qp, Wk, bk, Kp, Wv, bv, Vp);

    token_kernel<<<NBHT/8, 256>>>(Wta, bta, Wtb, btb);

    cand_scores<<<dim3(16, 8, 16), 256, CS_SMEM>>>();

    attn_kernel<<<NBHT/8, 256>>>();

    gemm_bias3<<<dim3(8, 16, 1), 256>>>(Cbp, Wo, bo, (float*)d_out,
                                        Wo, bo, (float*)d_out, Wo, bo, (float*)d_out);
}